// round 4
// baseline (speedup 1.0000x reference)
#include <cuda_runtime.h>

// NeuralODEClassifier: 4 threads per element ("quad"); each thread owns 16 of
// the 64 hidden units with ODE weights held in REGISTERS (no LDS in the step
// loop). Per-step quad reduction via shfl_xor (deterministic, so ya/yb stay
// replicated in all 4 lanes). Classifier fused: each lane computes h1 fully,
// then 16 of 64 h2 units; quad-reduces the 3 logits.
//
// tanh(z) = 1 - 2/(2^(C*z)+1), C = 2*log2(e); W1/b1 prescaled by C, the
// (1-2r) fold absorbed into W2 (v = -2*W2, S = colsum(W2)+b2).

#define H 64
#define UPT 16          // hidden units per thread
#define TT 64
#define NCLS 3
#define BLOCK 256

__device__ __forceinline__ float fast_ex2(float x) {
    float r; asm("ex2.approx.f32 %0, %1;" : "=f"(r) : "f"(x)); return r;
}
__device__ __forceinline__ float fast_rcp(float x) {
    float r; asm("rcp.approx.f32 %0, %1;" : "=f"(r) : "f"(x)); return r;
}

__global__ __launch_bounds__(BLOCK, 7)
void node_fused_kernel(
    const float* __restrict__ y0g,  const float* __restrict__ tg,
    const float* __restrict__ W1,   const float* __restrict__ b1,
    const float* __restrict__ W2,   const float* __restrict__ b2,
    const float* __restrict__ Wc1,  const float* __restrict__ bc1,
    const float* __restrict__ Wc2,  const float* __restrict__ bc2,
    const float* __restrict__ Wc3,  const float* __restrict__ bc3,
    float* __restrict__ out, int B)
{
    __shared__ float sW1zA[H], sW1zB[H], sb1z[H];
    __shared__ float sW2n0[H], sW2n1[H];          // -2*W2[u][0], -2*W2[u][1]
    __shared__ float sS[2];                       // colsum(W2) + b2
    __shared__ float sdt[TT - 1];
    __shared__ float sWc1A[H], sWc1B[H], sbc1[H], sbc2[H];
    __shared__ __align__(16) float sWc2T[H][H];   // [j][k]
    __shared__ __align__(16) float4 sWc3[H];      // {w0,w1,w2,0}
    __shared__ float sbc3[NCLS];

    const float C = 2.88539008177792681472f;      // 2*log2(e)
    const int tid = threadIdx.x;

    if (tid < H) {
        sW1zA[tid] = W1[tid] * C;
        sW1zB[tid] = W1[H + tid] * C;
        sb1z[tid]  = b1[tid] * C;
        sW2n0[tid] = -2.0f * W2[tid * 2 + 0];
        sW2n1[tid] = -2.0f * W2[tid * 2 + 1];
        sWc1A[tid] = Wc1[tid];
        sWc1B[tid] = Wc1[H + tid];
        sbc1[tid]  = bc1[tid];
        sbc2[tid]  = bc2[tid];
        sWc3[tid]  = make_float4(Wc3[tid * 3 + 0], Wc3[tid * 3 + 1],
                                 Wc3[tid * 3 + 2], 0.0f);
    }
    if (tid >= H && tid < H + 2) {
        int c = tid - H;
        float s = b2[c];
        #pragma unroll 8
        for (int j = 0; j < H; j++) s += W2[j * 2 + c];
        sS[c] = s;
    }
    if (tid >= 128 && tid < 128 + TT - 1) sdt[tid - 128] = tg[tid - 127] - tg[tid - 128];
    if (tid >= 192 && tid < 192 + NCLS)   sbc3[tid - 192] = bc3[tid - 192];
    for (int i = tid; i < H * H; i += BLOCK) {
        sWc2T[i & 63][i >> 6] = Wc2[i];           // Wc2 is [k][j] row-major
    }
    __syncthreads();

    const int gid = blockIdx.x * BLOCK + tid;
    const int e = gid >> 2;                       // element index
    const int q = gid & 3;                        // quad slot 0..3
    if (e >= B) return;

    // ---- stage this thread's 16-unit weight slice into registers ----
    const int u0 = q * UPT;
    float wa[UPT], wb[UPT], bb[UPT], v0[UPT], v1[UPT];
    #pragma unroll
    for (int i = 0; i < UPT; i++) {
        wa[i] = sW1zA[u0 + i];
        wb[i] = sW1zB[u0 + i];
        bb[i] = sb1z[u0 + i];
        v0[i] = sW2n0[u0 + i];
        v1[i] = sW2n1[u0 + i];
    }
    const float S0 = sS[0], S1 = sS[1];

    float ya = y0g[e * 2 + 0];
    float yb = y0g[e * 2 + 1];

    // ---- 63 Euler steps ----
    for (int s = 0; s < TT - 1; s++) {
        const float dt = sdt[s];
        float p00 = 0.f, p01 = 0.f, p10 = 0.f, p11 = 0.f;
        #pragma unroll
        for (int i = 0; i < UPT; i += 2) {
            float w0 = fmaf(ya, wa[i],     fmaf(yb, wb[i],     bb[i]));
            float w1 = fmaf(ya, wa[i + 1], fmaf(yb, wb[i + 1], bb[i + 1]));
            float r0 = fast_rcp(fast_ex2(w0) + 1.0f);
            float r1 = fast_rcp(fast_ex2(w1) + 1.0f);
            p00 = fmaf(r0, v0[i],     p00);
            p10 = fmaf(r0, v1[i],     p10);
            p01 = fmaf(r1, v0[i + 1], p01);
            p11 = fmaf(r1, v1[i + 1], p11);
        }
        float acc0 = p00 + p01;
        float acc1 = p10 + p11;
        acc0 += __shfl_xor_sync(0xffffffffu, acc0, 1);
        acc0 += __shfl_xor_sync(0xffffffffu, acc0, 2);
        acc1 += __shfl_xor_sync(0xffffffffu, acc1, 1);
        acc1 += __shfl_xor_sync(0xffffffffu, acc1, 2);
        ya = fmaf(dt, S0 + acc0, ya);             // identical in all 4 lanes
        yb = fmaf(dt, S1 + acc1, yb);
    }

    // ---- classifier (ya/yb replicated; each lane does 16 of 64 h2 units) ----
    float h1[H];
    #pragma unroll
    for (int j = 0; j < H; j++)
        h1[j] = fmaxf(fmaf(ya, sWc1A[j], fmaf(yb, sWc1B[j], sbc1[j])), 0.0f);

    float o0 = 0.f, o1 = 0.f, o2 = 0.f;
    const int j0 = q * UPT;
    #pragma unroll
    for (int jj = 0; jj < UPT; jj++) {
        const int j = j0 + jj;
        float s0 = sbc2[j], s1 = 0.f, s2 = 0.f, s3 = 0.f;
        #pragma unroll
        for (int k = 0; k < H; k += 4) {
            const float4 w = *(const float4*)&sWc2T[j][k];
            s0 = fmaf(h1[k + 0], w.x, s0);
            s1 = fmaf(h1[k + 1], w.y, s1);
            s2 = fmaf(h1[k + 2], w.z, s2);
            s3 = fmaf(h1[k + 3], w.w, s3);
        }
        float hv = fmaxf((s0 + s1) + (s2 + s3), 0.0f);
        const float4 wc = sWc3[j];
        o0 = fmaf(hv, wc.x, o0);
        o1 = fmaf(hv, wc.y, o1);
        o2 = fmaf(hv, wc.z, o2);
    }
    o0 += __shfl_xor_sync(0xffffffffu, o0, 1);
    o0 += __shfl_xor_sync(0xffffffffu, o0, 2);
    o1 += __shfl_xor_sync(0xffffffffu, o1, 1);
    o1 += __shfl_xor_sync(0xffffffffu, o1, 2);
    o2 += __shfl_xor_sync(0xffffffffu, o2, 1);
    o2 += __shfl_xor_sync(0xffffffffu, o2, 2);

    if (q == 0) {
        out[e * 3 + 0] = o0 + sbc3[0];
        out[e * 3 + 1] = o1 + sbc3[1];
        out[e * 3 + 2] = o2 + sbc3[2];
    }
}

extern "C" void kernel_launch(void* const* d_in, const int* in_sizes, int n_in,
                              void* d_out, int out_size) {
    const float* y0  = (const float*)d_in[0];
    const float* t   = (const float*)d_in[1];
    const float* W1  = (const float*)d_in[2];
    const float* b1  = (const float*)d_in[3];
    const float* W2  = (const float*)d_in[4];
    const float* b2  = (const float*)d_in[5];
    const float* Wc1 = (const float*)d_in[6];
    const float* bc1 = (const float*)d_in[7];
    const float* Wc2 = (const float*)d_in[8];
    const float* bc2 = (const float*)d_in[9];
    const float* Wc3 = (const float*)d_in[10];
    const float* bc3 = (const float*)d_in[11];
    float* out = (float*)d_out;

    const int B = in_sizes[0] / 2;
    const long long threads = (long long)B * 4;
    const int grid = (int)((threads + BLOCK - 1) / BLOCK);
    node_fused_kernel<<<grid, BLOCK>>>(y0, t, W1, b1, W2, b2,
                                       Wc1, bc1, Wc2, bc2, Wc3, bc3,
                                       out, B);
}

// round 5
// speedup vs baseline: 1.7002x; 1.7002x over previous
#include <cuda_runtime.h>

// NeuralODEClassifier, two kernels:
//  K1 (ODE): 4 threads/elem, 16 hidden units/thread, weights in SHARED with
//            bank-conflict-free [group][quad] float4 packing. ~28 live regs ->
//            7 CTAs/SM resident -> single wave, MUFU-bound.
//  K2 (classifier): 1 thread/elem, Wc2 transposed in shared (R2 version).
//
// tanh(z) = 1 - 2/(2^(C*z)+1), C = 2*log2(e); W1/b1 prescaled by C, the
// (1-2r) fold absorbed into W2 (v = -2*W2, S = colsum(W2)+b2).

#define H 64
#define TT 64
#define NCLS 3
#define BMAX 65536

__device__ float g_yT[BMAX * 2];

__device__ __forceinline__ float fast_ex2(float x) {
    float r; asm("ex2.approx.f32 %0, %1;" : "=f"(r) : "f"(x)); return r;
}
__device__ __forceinline__ float fast_rcp(float x) {
    float r; asm("rcp.approx.f32 %0, %1;" : "=f"(r) : "f"(x)); return r;
}

// ---------------------------------------------------------------- K1: ODE ---
// Packed layout: idx(u) with u = q*16 + 4*g + c  ->  float4 slot (g*4 + q),
// component c.  For fixed g, the 4 quad-lanes read 4 consecutive float4s
// (64B, disjoint banks) and 8 lanes share each address (broadcast).
#define PK(g, q, c) (((g) * 4 + (q)) * 4 + (c))

__global__ __launch_bounds__(256, 7)
void node_ode_kernel(
    const float* __restrict__ y0g,  const float* __restrict__ tg,
    const float* __restrict__ W1,   const float* __restrict__ b1,
    const float* __restrict__ W2,   const float* __restrict__ b2,
    int B)
{
    __shared__ __align__(16) float sWA[H];   // W1 row0 * C, packed
    __shared__ __align__(16) float sWB[H];   // W1 row1 * C, packed
    __shared__ __align__(16) float sBB[H];   // b1 * C, packed
    __shared__ __align__(16) float sV0[H];   // -2*W2[u][0], packed
    __shared__ __align__(16) float sV1[H];   // -2*W2[u][1], packed
    __shared__ float sS[2];
    __shared__ float sdt[TT - 1];

    const float C = 2.88539008177792681472f; // 2*log2(e)
    const int tid = threadIdx.x;

    if (tid < H) {
        int u = tid;
        int q = u >> 4, r = u & 15, g = r >> 2, c = r & 3;
        int p = PK(g, q, c);
        sWA[p] = W1[u] * C;
        sWB[p] = W1[H + u] * C;
        sBB[p] = b1[u] * C;
        sV0[p] = -2.0f * W2[u * 2 + 0];
        sV1[p] = -2.0f * W2[u * 2 + 1];
    }
    if (tid >= H && tid < H + 2) {
        int c = tid - H;
        float s = b2[c];
        #pragma unroll 8
        for (int j = 0; j < H; j++) s += W2[j * 2 + c];
        sS[c] = s;
    }
    if (tid >= 128 && tid < 128 + TT - 1)
        sdt[tid - 128] = tg[tid - 127] - tg[tid - 128];
    __syncthreads();

    const int gid = blockIdx.x * 256 + tid;
    const int e = gid >> 2;
    const int q = gid & 3;
    if (e >= B) return;

    float ya = y0g[e * 2 + 0];
    float yb = y0g[e * 2 + 1];
    const float S0 = sS[0], S1 = sS[1];

    for (int s = 0; s < TT - 1; s++) {
        const float dt = sdt[s];
        float acc0 = 0.f, acc1 = 0.f;
        #pragma unroll
        for (int g = 0; g < 4; g++) {
            const float4 wa = *(const float4*)&sWA[PK(g, q, 0)];
            const float4 wb = *(const float4*)&sWB[PK(g, q, 0)];
            const float4 bb = *(const float4*)&sBB[PK(g, q, 0)];
            const float4 v0 = *(const float4*)&sV0[PK(g, q, 0)];
            const float4 v1 = *(const float4*)&sV1[PK(g, q, 0)];

            float w0 = fmaf(ya, wa.x, fmaf(yb, wb.x, bb.x));
            float w1 = fmaf(ya, wa.y, fmaf(yb, wb.y, bb.y));
            float w2 = fmaf(ya, wa.z, fmaf(yb, wb.z, bb.z));
            float w3 = fmaf(ya, wa.w, fmaf(yb, wb.w, bb.w));

            float r0 = fast_rcp(fast_ex2(w0) + 1.0f);
            float r1 = fast_rcp(fast_ex2(w1) + 1.0f);
            float r2 = fast_rcp(fast_ex2(w2) + 1.0f);
            float r3 = fast_rcp(fast_ex2(w3) + 1.0f);

            acc0 = fmaf(r0, v0.x, acc0); acc1 = fmaf(r0, v1.x, acc1);
            acc0 = fmaf(r1, v0.y, acc0); acc1 = fmaf(r1, v1.y, acc1);
            acc0 = fmaf(r2, v0.z, acc0); acc1 = fmaf(r2, v1.z, acc1);
            acc0 = fmaf(r3, v0.w, acc0); acc1 = fmaf(r3, v1.w, acc1);
        }
        acc0 += __shfl_xor_sync(0xffffffffu, acc0, 1);
        acc0 += __shfl_xor_sync(0xffffffffu, acc0, 2);
        acc1 += __shfl_xor_sync(0xffffffffu, acc1, 1);
        acc1 += __shfl_xor_sync(0xffffffffu, acc1, 2);
        ya = fmaf(dt, S0 + acc0, ya);    // identical across the quad
        yb = fmaf(dt, S1 + acc1, yb);
    }

    if (q == 0) {
        g_yT[e * 2 + 0] = ya;
        g_yT[e * 2 + 1] = yb;
    }
}

// --------------------------------------------------------- K2: classifier ---
__global__ __launch_bounds__(128, 4)
void node_cls_kernel(
    const float* __restrict__ Wc1,  const float* __restrict__ bc1,
    const float* __restrict__ Wc2,  const float* __restrict__ bc2,
    const float* __restrict__ Wc3,  const float* __restrict__ bc3,
    float* __restrict__ out, int B)
{
    __shared__ __align__(16) float sWc1A[H], sWc1B[H], sbc1[H];
    __shared__ __align__(16) float sWc2T[H][H];  // [out_j][in_k]
    __shared__ __align__(16) float sbc2[H];
    __shared__ __align__(16) float4 sWc3[H];     // {w0,w1,w2,0}
    __shared__ float sbc3[NCLS];

    const int tid = threadIdx.x;
    if (tid < H) {
        sWc1A[tid] = Wc1[tid];
        sWc1B[tid] = Wc1[H + tid];
        sbc1[tid]  = bc1[tid];
        sbc2[tid]  = bc2[tid];
        sWc3[tid]  = make_float4(Wc3[tid * 3 + 0], Wc3[tid * 3 + 1],
                                 Wc3[tid * 3 + 2], 0.0f);
    }
    if (tid < NCLS) sbc3[tid] = bc3[tid];
    for (int i = tid; i < H * H; i += 128) {
        sWc2T[i & 63][i >> 6] = Wc2[i];
    }
    __syncthreads();

    const int idx = blockIdx.x * 128 + tid;
    if (idx >= B) return;

    const float ya = g_yT[idx * 2 + 0];
    const float yb = g_yT[idx * 2 + 1];

    float h1[H];
    #pragma unroll
    for (int j = 0; j < H; j++)
        h1[j] = fmaxf(fmaf(ya, sWc1A[j], fmaf(yb, sWc1B[j], sbc1[j])), 0.0f);

    float o0 = sbc3[0], o1 = sbc3[1], o2 = sbc3[2];
    for (int j = 0; j < H; j++) {
        float s0 = sbc2[j], s1 = 0.f, s2 = 0.f, s3 = 0.f;
        #pragma unroll
        for (int k = 0; k < H; k += 4) {
            const float4 w = *(const float4*)&sWc2T[j][k];
            s0 = fmaf(h1[k + 0], w.x, s0);
            s1 = fmaf(h1[k + 1], w.y, s1);
            s2 = fmaf(h1[k + 2], w.z, s2);
            s3 = fmaf(h1[k + 3], w.w, s3);
        }
        float s = fmaxf((s0 + s1) + (s2 + s3), 0.0f);
        const float4 wc = sWc3[j];
        o0 = fmaf(s, wc.x, o0);
        o1 = fmaf(s, wc.y, o1);
        o2 = fmaf(s, wc.z, o2);
    }

    out[idx * 3 + 0] = o0;
    out[idx * 3 + 1] = o1;
    out[idx * 3 + 2] = o2;
}

extern "C" void kernel_launch(void* const* d_in, const int* in_sizes, int n_in,
                              void* d_out, int out_size) {
    const float* y0  = (const float*)d_in[0];
    const float* t   = (const float*)d_in[1];
    const float* W1  = (const float*)d_in[2];
    const float* b1  = (const float*)d_in[3];
    const float* W2  = (const float*)d_in[4];
    const float* b2  = (const float*)d_in[5];
    const float* Wc1 = (const float*)d_in[6];
    const float* bc1 = (const float*)d_in[7];
    const float* Wc2 = (const float*)d_in[8];
    const float* bc2 = (const float*)d_in[9];
    const float* Wc3 = (const float*)d_in[10];
    const float* bc3 = (const float*)d_in[11];
    float* out = (float*)d_out;

    const int B = in_sizes[0] / 2;
    const long long th = (long long)B * 4;
    node_ode_kernel<<<(int)((th + 255) / 256), 256>>>(y0, t, W1, b1, W2, b2, B);
    node_cls_kernel<<<(B + 127) / 128, 128>>>(Wc1, bc1, Wc2, bc2, Wc3, bc3, out, B);
}

// round 6
// speedup vs baseline: 1.7854x; 1.0501x over previous
#include <cuda_runtime.h>

// NeuralODEClassifier, two kernels.
// K1 (ODE): 2 threads/elem, 32 hidden units/thread. Per 4-unit group, ONE
//   rcp serves 4 sigmoids (cofactor trick); w-MLP and accumulation use packed
//   fma.rn.f32x2. Weights in shared, packed so the two pair-lanes hit
//   different banks. w clamped <= 30 so batched products can't overflow.
// K2 (classifier): 1 thread/elem, Wc2 transposed in shared.
//
// tanh(z) = 1 - 2/(2^(C*z)+1), C = 2*log2(e); W1/b1 prescaled by C, the
// (1-2r) fold absorbed into W2 (vv = -2*W2, S = colsum(W2)+b2).

#define H 64
#define TT 64
#define NCLS 3
#define BMAX 65536

typedef unsigned long long u64;

__device__ float g_yT[BMAX * 2];

__device__ __forceinline__ float fast_ex2(float x) {
    float r; asm("ex2.approx.f32 %0, %1;" : "=f"(r) : "f"(x)); return r;
}
__device__ __forceinline__ float fast_rcp(float x) {
    float r; asm("rcp.approx.f32 %0, %1;" : "=f"(r) : "f"(x)); return r;
}
__device__ __forceinline__ u64 pk2(float lo, float hi) {
    u64 r; asm("mov.b64 %0, {%1, %2};" : "=l"(r) : "f"(lo), "f"(hi)); return r;
}
__device__ __forceinline__ void unpk2(u64 v, float& lo, float& hi) {
    asm("mov.b64 {%0, %1}, %2;" : "=f"(lo), "=f"(hi) : "l"(v));
}
__device__ __forceinline__ u64 fma2(u64 a, u64 b, u64 c) {
    u64 d; asm("fma.rn.f32x2 %0, %1, %2, %3;" : "=l"(d) : "l"(a), "l"(b), "l"(c));
    return d;
}
__device__ __forceinline__ u64 add2(u64 a, u64 b) {
    u64 d; asm("add.rn.f32x2 %0, %1, %2;" : "=l"(d) : "l"(a), "l"(b));
    return d;
}

// ---------------------------------------------------------------- K1: ODE ---
// Packing: unit u (0..63): q=u>>5, r=u&31, g=r>>2, c=r&3 -> slot (g*2+q)*4+c.
// For a given group g, lane-parity 0 reads 16B at (g*2)*16, parity 1 at
// (g*2+1)*16 -> adjacent 16B chunks, different banks, broadcast across warp.
#define SLOT(g, q, c) (((g) * 2 + (q)) * 4 + (c))

__global__ __launch_bounds__(256, 4)
void node_ode_kernel(
    const float* __restrict__ y0g,  const float* __restrict__ tg,
    const float* __restrict__ W1,   const float* __restrict__ b1,
    const float* __restrict__ W2,   const float* __restrict__ b2,
    int B)
{
    __shared__ __align__(16) float sWA[H];    // W1 row0 * C, packed
    __shared__ __align__(16) float sWB[H];    // W1 row1 * C, packed
    __shared__ __align__(16) float sBB[H];    // b1 * C, packed
    __shared__ __align__(16) float2 sVV[H];   // {-2*W2[u][0], -2*W2[u][1]}, packed
    __shared__ float sS[2];
    __shared__ float sdt[TT - 1];

    const float C = 2.88539008177792681472f;  // 2*log2(e)
    const int tid = threadIdx.x;

    if (tid < H) {
        int u = tid;
        int q = u >> 5, r = u & 31, g = r >> 2, c = r & 3;
        int p = SLOT(g, q, c);
        sWA[p] = W1[u] * C;
        sWB[p] = W1[H + u] * C;
        sBB[p] = b1[u] * C;
        sVV[p] = make_float2(-2.0f * W2[u * 2 + 0], -2.0f * W2[u * 2 + 1]);
    }
    if (tid >= H && tid < H + 2) {
        int c = tid - H;
        float s = b2[c];
        #pragma unroll 8
        for (int j = 0; j < H; j++) s += W2[j * 2 + c];
        sS[c] = s;
    }
    if (tid >= 128 && tid < 128 + TT - 1)
        sdt[tid - 128] = tg[tid - 127] - tg[tid - 128];
    __syncthreads();

    const int gid = blockIdx.x * 256 + tid;
    const int e = gid >> 1;          // element index
    const int q = gid & 1;           // pair slot
    if (e >= B) return;

    float ya = y0g[e * 2 + 0];
    float yb = y0g[e * 2 + 1];
    const float S0 = sS[0], S1 = sS[1];

    for (int s = 0; s < TT - 1; s++) {
        const float dt = sdt[s];
        const u64 ya2 = pk2(ya, ya);
        const u64 yb2 = pk2(yb, yb);
        u64 accA = 0, accB = 0, accC = 0, accD = 0;  // {acc0, acc1} pairs

        #pragma unroll
        for (int g = 0; g < 8; g++) {
            const int base = SLOT(g, q, 0);
            const ulonglong2 WA = *(const ulonglong2*)&sWA[base];
            const ulonglong2 WB = *(const ulonglong2*)&sWB[base];
            const ulonglong2 BB = *(const ulonglong2*)&sBB[base];

            u64 w01 = fma2(ya2, WA.x, fma2(yb2, WB.x, BB.x));
            u64 w23 = fma2(ya2, WA.y, fma2(yb2, WB.y, BB.y));
            float w0, w1, w2, w3;
            unpk2(w01, w0, w1);
            unpk2(w23, w2, w3);
            // upper clamp only: very negative w underflows ex2 to 0 (exact).
            w0 = fminf(w0, 30.0f); w1 = fminf(w1, 30.0f);
            w2 = fminf(w2, 30.0f); w3 = fminf(w3, 30.0f);

            float a0 = fast_ex2(w0) + 1.0f;
            float a1 = fast_ex2(w1) + 1.0f;
            float a2 = fast_ex2(w2) + 1.0f;
            float a3 = fast_ex2(w3) + 1.0f;

            float p01 = a0 * a1, p23 = a2 * a3;
            float rinv = fast_rcp(p01 * p23);
            float q01 = rinv * p23, q23 = rinv * p01;
            float r0 = q01 * a1, r1 = q01 * a0;
            float r2 = q23 * a3, r3 = q23 * a2;

            const ulonglong2 V01 = *(const ulonglong2*)&sVV[base];
            const ulonglong2 V23 = *(const ulonglong2*)&sVV[base + 2];
            accA = fma2(pk2(r0, r0), V01.x, accA);
            accB = fma2(pk2(r1, r1), V01.y, accB);
            accC = fma2(pk2(r2, r2), V23.x, accC);
            accD = fma2(pk2(r3, r3), V23.y, accD);
        }

        float acc0, acc1;
        unpk2(add2(add2(accA, accB), add2(accC, accD)), acc0, acc1);
        acc0 += __shfl_xor_sync(0xffffffffu, acc0, 1);
        acc1 += __shfl_xor_sync(0xffffffffu, acc1, 1);
        ya = fmaf(dt, S0 + acc0, ya);   // identical in both pair lanes
        yb = fmaf(dt, S1 + acc1, yb);
    }

    if (q == 0) {
        g_yT[e * 2 + 0] = ya;
        g_yT[e * 2 + 1] = yb;
    }
}

// --------------------------------------------------------- K2: classifier ---
__global__ __launch_bounds__(128, 4)
void node_cls_kernel(
    const float* __restrict__ Wc1,  const float* __restrict__ bc1,
    const float* __restrict__ Wc2,  const float* __restrict__ bc2,
    const float* __restrict__ Wc3,  const float* __restrict__ bc3,
    float* __restrict__ out, int B)
{
    __shared__ __align__(16) float sWc1A[H], sWc1B[H], sbc1[H];
    __shared__ __align__(16) float sWc2T[H][H];  // [out_j][in_k]
    __shared__ __align__(16) float sbc2[H];
    __shared__ __align__(16) float4 sWc3[H];     // {w0,w1,w2,0}
    __shared__ float sbc3[NCLS];

    const int tid = threadIdx.x;
    if (tid < H) {
        sWc1A[tid] = Wc1[tid];
        sWc1B[tid] = Wc1[H + tid];
        sbc1[tid]  = bc1[tid];
        sbc2[tid]  = bc2[tid];
        sWc3[tid]  = make_float4(Wc3[tid * 3 + 0], Wc3[tid * 3 + 1],
                                 Wc3[tid * 3 + 2], 0.0f);
    }
    if (tid < NCLS) sbc3[tid] = bc3[tid];
    for (int i = tid; i < H * H; i += 128) {
        sWc2T[i & 63][i >> 6] = Wc2[i];
    }
    __syncthreads();

    const int idx = blockIdx.x * 128 + tid;
    if (idx >= B) return;

    const float ya = g_yT[idx * 2 + 0];
    const float yb = g_yT[idx * 2 + 1];

    float h1[H];
    #pragma unroll
    for (int j = 0; j < H; j++)
        h1[j] = fmaxf(fmaf(ya, sWc1A[j], fmaf(yb, sWc1B[j], sbc1[j])), 0.0f);

    float o0 = sbc3[0], o1 = sbc3[1], o2 = sbc3[2];
    for (int j = 0; j < H; j++) {
        float s0 = sbc2[j], s1 = 0.f, s2 = 0.f, s3 = 0.f;
        #pragma unroll
        for (int k = 0; k < H; k += 4) {
            const float4 w = *(const float4*)&sWc2T[j][k];
            s0 = fmaf(h1[k + 0], w.x, s0);
            s1 = fmaf(h1[k + 1], w.y, s1);
            s2 = fmaf(h1[k + 2], w.z, s2);
            s3 = fmaf(h1[k + 3], w.w, s3);
        }
        float s = fmaxf((s0 + s1) + (s2 + s3), 0.0f);
        const float4 wc = sWc3[j];
        o0 = fmaf(s, wc.x, o0);
        o1 = fmaf(s, wc.y, o1);
        o2 = fmaf(s, wc.z, o2);
    }

    out[idx * 3 + 0] = o0;
    out[idx * 3 + 1] = o1;
    out[idx * 3 + 2] = o2;
}

extern "C" void kernel_launch(void* const* d_in, const int* in_sizes, int n_in,
                              void* d_out, int out_size) {
    const float* y0  = (const float*)d_in[0];
    const float* t   = (const float*)d_in[1];
    const float* W1  = (const float*)d_in[2];
    const float* b1  = (const float*)d_in[3];
    const float* W2  = (const float*)d_in[4];
    const float* b2  = (const float*)d_in[5];
    const float* Wc1 = (const float*)d_in[6];
    const float* bc1 = (const float*)d_in[7];
    const float* Wc2 = (const float*)d_in[8];
    const float* bc2 = (const float*)d_in[9];
    const float* Wc3 = (const float*)d_in[10];
    const float* bc3 = (const float*)d_in[11];
    float* out = (float*)d_out;

    const int B = in_sizes[0] / 2;
    const long long th = (long long)B * 2;
    node_ode_kernel<<<(int)((th + 255) / 256), 256>>>(y0, t, W1, b1, W2, b2, B);
    node_cls_kernel<<<(B + 127) / 128, 128>>>(Wc1, bc1, Wc2, bc2, Wc3, bc3, out, B);
}